// round 3
// baseline (speedup 1.0000x reference)
#include <cuda_runtime.h>
#include <cstdint>

// ---------------------------------------------------------------------------
// Problem constants
// ---------------------------------------------------------------------------
constexpr int BB = 32, CC = 256, HH = 56, WW = 56;
constexpr int HP = 58, WP = 58;                 // padded spatial
constexpr int HWs = HH * WW;                    // 3136
constexpr int CHW = CC * HWs;                   // 802816
constexpr int PIX = BB * HWs;                   // 100352
constexpr int KD  = 2304;                       // Cin * 9
constexpr int TILE_M = 128;
constexpr int TILE_N = 128;
constexpr int NTILES = PIX / TILE_M;            // 784
constexpr int NCHUNK = KD / 64;                 // 36 chunks of 64 int8
constexpr float BN_EPS = 1e-5f;

// smem row stride (bytes): 64 data bytes padded to 80 -> ldmatrix row
// addresses (stride 80B = 20 banks) hit distinct bank groups, conflict-free.
constexpr int SSTR = 80;
constexpr int ABYTES = TILE_M * SSTR;           // 10240
constexpr int BBYTES = TILE_N * SSTR;           // 10240
constexpr int STAGES = 4;
constexpr int SMEM_DYN = STAGES * (ABYTES + BBYTES);  // 81920

// ---------------------------------------------------------------------------
// Device scratch (allocation-free: __device__ globals)
// ---------------------------------------------------------------------------
__device__ uint4 g_xa_raw[(size_t)BB * HP * WP * CC / 16];  // int8 padded NHWC, 27.5MB
__device__ uint4 g_wb_raw[(size_t)CC * KD / 16];            // int8 [co][tap*256+ci], 590KB
__device__ float g_y[(size_t)PIX * CC];                     // conv accum (unscaled), NCHW
__device__ float g_scale[CC];
__device__ float g_sum[CC];
__device__ float g_sumsq[CC];
__device__ float g_ab[2 * CC];

#define G_XA ((int8_t*)g_xa_raw)
#define G_WB ((int8_t*)g_wb_raw)

// ---------------------------------------------------------------------------
// PTX helpers (all baseline, assemble at .target sm_103)
// ---------------------------------------------------------------------------
__device__ __forceinline__ uint32_t smem_to_u32(const void* p) {
    uint32_t a;
    asm("{ .reg .u64 t; cvta.to.shared.u64 t, %1; cvt.u32.u64 %0, t; }" : "=r"(a) : "l"(p));
    return a;
}
__device__ __forceinline__ void cp16(uint32_t dst, const void* src) {
    asm volatile("cp.async.cg.shared.global [%0], [%1], 16;" :: "r"(dst), "l"(src));
}
#define CP_COMMIT() asm volatile("cp.async.commit_group;" ::: "memory")
#define CP_WAIT2()  asm volatile("cp.async.wait_group 2;" ::: "memory")

__device__ __forceinline__ void ldsm4(uint32_t& r0, uint32_t& r1, uint32_t& r2,
                                      uint32_t& r3, uint32_t addr) {
    asm volatile("ldmatrix.sync.aligned.m8n8.x4.shared.b16 {%0,%1,%2,%3}, [%4];"
                 : "=r"(r0), "=r"(r1), "=r"(r2), "=r"(r3) : "r"(addr));
}
__device__ __forceinline__ void mma_s8(int* d, uint32_t a0, uint32_t a1,
                                       uint32_t a2, uint32_t a3,
                                       uint32_t b0, uint32_t b1) {
    asm volatile(
        "mma.sync.aligned.m16n8k32.row.col.s32.s8.s8.s32 "
        "{%0,%1,%2,%3}, {%4,%5,%6,%7}, {%8,%9}, {%0,%1,%2,%3};"
        : "+r"(d[0]), "+r"(d[1]), "+r"(d[2]), "+r"(d[3])
        : "r"(a0), "r"(a1), "r"(a2), "r"(a3), "r"(b0), "r"(b1));
}

// ---------------------------------------------------------------------------
// Kernel: weight scale (mean |w| per Cout) + int8 signs + zero BN accumulators
// ---------------------------------------------------------------------------
__global__ void wprep_kernel(const float* __restrict__ w) {
    int o = blockIdx.x, tid = threadIdx.x;
    if (tid == 0) { g_sum[o] = 0.0f; g_sumsq[o] = 0.0f; }
    const float* wp = w + ((size_t)o * CC + tid) * 9;
    float v[9]; float s = 0.0f;
#pragma unroll
    for (int t = 0; t < 9; t++) { v[t] = wp[t]; s += fabsf(v[t]); }
#pragma unroll
    for (int off = 16; off; off >>= 1) s += __shfl_xor_sync(~0u, s, off);
    __shared__ float sh[8];
    if ((tid & 31) == 0) sh[tid >> 5] = s;
    __syncthreads();
    if (tid == 0) {
        float t = 0.0f;
        for (int i = 0; i < 8; i++) t += sh[i];
        g_scale[o] = t / (float)KD;
    }
#pragma unroll
    for (int t = 0; t < 9; t++) {
        float xv = v[t];
        int sg = (xv > 0.0f) ? 1 : ((xv < 0.0f) ? -1 : 0);
        G_WB[(size_t)o * KD + t * 256 + tid] = (int8_t)sg;
    }
}

// ---------------------------------------------------------------------------
// Kernel: zero padded border of xa
// ---------------------------------------------------------------------------
__global__ void border_kernel() {
    int i = blockIdx.x, b = blockIdx.y;
    int h, w;
    if (i < 58)       { h = 0;           w = i; }
    else if (i < 116) { h = 57;          w = i - 58; }
    else if (i < 172) { h = i - 116 + 1; w = 0; }
    else              { h = i - 172 + 1; w = 57; }
    G_XA[(((size_t)(b * HP + h) * WP + w) * CC) + threadIdx.x] = 0;
}

// ---------------------------------------------------------------------------
// Kernel: sign(x), NCHW fp32 -> padded NHWC int8 (smem transpose, packed u32)
// ---------------------------------------------------------------------------
__global__ void sign_transpose_kernel(const float* __restrict__ x) {
    int h = blockIdx.x, b = blockIdx.y;
    __shared__ float tile[64][57];
    int tid = threadIdx.x;
    for (int cb = 0; cb < 4; cb++) {
        for (int idx = tid; idx < 64 * 56; idx += 256) {
            int ci = idx / 56, w = idx - ci * 56;
            tile[ci][w] = x[((size_t)(b * CC + cb * 64 + ci) * HH + h) * WW + w];
        }
        __syncthreads();
        for (int idx = tid; idx < 56 * 16; idx += 256) {
            int w = idx >> 4, g = idx & 15;
            uint32_t packed = 0;
#pragma unroll
            for (int k = 0; k < 4; k++) {
                float v = tile[g * 4 + k][w];
                int s = (v > 0.0f) ? 1 : ((v < 0.0f) ? -1 : 0);
                packed |= (uint32_t)((uint8_t)(int8_t)s) << (k * 8);
            }
            *(uint32_t*)&G_XA[(((size_t)(b * HP + h + 1) * WP + (w + 1)) * CC) +
                              cb * 64 + g * 4] = packed;
        }
        __syncthreads();
    }
}

// ---------------------------------------------------------------------------
// Kernel: implicit-GEMM conv, CTA tile M=128 x N=128, K=2304, int8 IMMA.
// cp.async 4-stage pipeline + ldmatrix fragment loads + fused BN stats.
// ---------------------------------------------------------------------------
__global__ __launch_bounds__(256) void gemm_kernel() {
    extern __shared__ char smem[];
    const uint32_t saB = smem_to_u32(smem);                 // A stages base
    const uint32_t sbB = saB + STAGES * ABYTES;             // B stages base

    const int tid = threadIdx.x;
    const int wid = tid >> 5;
    const int lane = tid & 31;
    const int wm = wid & 3;      // m-block of 32 rows
    const int wn = wid >> 2;     // n-block of 64 cols
    const int p0 = blockIdx.x * TILE_M;
    const int n0 = blockIdx.y * TILE_N;

    // staging: thread t copies 32B of row r (A: pixel row, B: cout row)
    const int r = tid >> 1, half = tid & 1;
    int p = p0 + r;
    int b = p / HWs; int hw = p - b * HWs;
    int h = hw / WW; int w = hw - h * WW;
    const int8_t* abase = G_XA + (((size_t)(b * HP + h) * WP + w) * CC) + half * 32;
    const int8_t* bbase = G_WB + (size_t)(n0 + r) * KD + half * 32;
    const uint32_t sdst = (uint32_t)(r * SSTR + half * 32);

    auto issue = [&](int kc, int buf) {
        int tap = kc >> 2;
        int ci0 = (kc & 3) * 64;
        int kh = tap / 3, kw = tap - 3 * kh;
        const int8_t* as = abase + ((kh * WP + kw) * CC + ci0);
        const int8_t* bs = bbase + tap * 256 + ci0;
        uint32_t da = saB + buf * ABYTES + sdst;
        uint32_t db = sbB + buf * BBYTES + sdst;
        cp16(da, as); cp16(da + 16, as + 16);
        cp16(db, bs); cp16(db + 16, bs + 16);
    };

    int acc[2][8][4];
#pragma unroll
    for (int mf = 0; mf < 2; mf++)
#pragma unroll
        for (int nf = 0; nf < 8; nf++)
#pragma unroll
            for (int i = 0; i < 4; i++) acc[mf][nf][i] = 0;

    // ldmatrix addresses: row = lane&15, k-half select = lane>>4
    const int lrow = lane & 15;
    const int lko  = (lane >> 4) * 16;
    const uint32_t aFragOff = (uint32_t)((wm * 32 + lrow) * SSTR + lko);
    const uint32_t bFragOff = (uint32_t)((wn * 64 + lrow) * SSTR + lko);

    // prologue: 3 stages in flight
#pragma unroll
    for (int st = 0; st < 3; st++) { issue(st, st); CP_COMMIT(); }

    for (int kc = 0; kc < NCHUNK; kc++) {
        const int buf = kc & 3;
        CP_WAIT2();
        __syncthreads();
        if (kc + 3 < NCHUNK) issue(kc + 3, (kc + 3) & 3);
        CP_COMMIT();  // empty group in the tail keeps wait_group 2 uniform

        const uint32_t sa = saB + buf * ABYTES;
        const uint32_t sb = sbB + buf * BBYTES;
#pragma unroll
        for (int s = 0; s < 2; s++) {
            uint32_t a[2][4];
#pragma unroll
            for (int mf = 0; mf < 2; mf++)
                ldsm4(a[mf][0], a[mf][1], a[mf][2], a[mf][3],
                      sa + aFragOff + mf * 16 * SSTR + s * 32);
#pragma unroll
            for (int nb = 0; nb < 4; nb++) {
                uint32_t b0, b1, b2, b3;
                ldsm4(b0, b1, b2, b3, sb + bFragOff + nb * 16 * SSTR + s * 32);
                // b0/b2: n-subtile even (rows nb*16..+7); b1/b3: odd (+8..15)
                mma_s8(acc[0][2 * nb],     a[0][0], a[0][1], a[0][2], a[0][3], b0, b2);
                mma_s8(acc[0][2 * nb + 1], a[0][0], a[0][1], a[0][2], a[0][3], b1, b3);
                mma_s8(acc[1][2 * nb],     a[1][0], a[1][1], a[1][2], a[1][3], b0, b2);
                mma_s8(acc[1][2 * nb + 1], a[1][0], a[1][1], a[1][2], a[1][3], b1, b3);
            }
        }
        __syncthreads();
    }

    // ---- Epilogue 1: fused BN statistics (per-channel sum / sumsq) ----
#pragma unroll
    for (int nf = 0; nf < 8; nf++) {
#pragma unroll
        for (int j = 0; j < 2; j++) {
            float s = 0.0f, s2 = 0.0f;
#pragma unroll
            for (int mf = 0; mf < 2; mf++) {
#pragma unroll
                for (int rh = 0; rh < 2; rh++) {
                    float v = (float)acc[mf][nf][rh * 2 + j];
                    s += v; s2 += v * v;
                }
            }
#pragma unroll
            for (int o = 4; o < 32; o <<= 1) {
                s  += __shfl_xor_sync(~0u, s, o);
                s2 += __shfl_xor_sync(~0u, s2, o);
            }
            if (lane < 4) {
                int c = n0 + wn * 64 + nf * 8 + 2 * lane + j;
                atomicAdd(&g_sum[c], s);
                atomicAdd(&g_sumsq[c], s2);
            }
        }
    }

    // ---- Epilogue 2: write conv accumulators to g_y (NCHW, fp32) ----
#pragma unroll
    for (int mf = 0; mf < 2; mf++) {
#pragma unroll
        for (int rh = 0; rh < 2; rh++) {
            int p2 = p0 + wm * 32 + mf * 16 + (lane >> 2) + rh * 8;
            int b2 = p2 / HWs; int hw2 = p2 - b2 * HWs;
            float* yd = g_y + (size_t)b2 * CHW + hw2;
#pragma unroll
            for (int nf = 0; nf < 8; nf++) {
                int c = n0 + wn * 64 + nf * 8 + 2 * (lane & 3);
                yd[(size_t)c * HWs]       = (float)acc[mf][nf][rh * 2 + 0];
                yd[(size_t)(c + 1) * HWs] = (float)acc[mf][nf][rh * 2 + 1];
            }
        }
    }
}

// ---------------------------------------------------------------------------
// Kernel: BN affine coefficients (weight scale folded in exactly)
// ---------------------------------------------------------------------------
__global__ void coeff_kernel(const float* __restrict__ gamma, const float* __restrict__ beta) {
    int c = threadIdx.x;
    float n  = (float)PIX;
    float mu = g_sum[c] / n;
    float vu = g_sumsq[c] / n - mu * mu;
    float sc = g_scale[c];
    float A  = gamma[c] * sc * rsqrtf(sc * sc * vu + BN_EPS);
    g_ab[c]      = A;
    g_ab[CC + c] = beta[c] - A * mu;
}

// ---------------------------------------------------------------------------
// Kernel: out = relu(A*u + B)   (vectorized, NCHW)
// ---------------------------------------------------------------------------
__global__ void finalize_kernel(float* __restrict__ out) {
    size_t n4 = (size_t)PIX * CC / 4;
    for (size_t i = (size_t)blockIdx.x * blockDim.x + threadIdx.x; i < n4;
         i += (size_t)gridDim.x * blockDim.x) {
        size_t j = i * 4;
        int c = (int)((j / HWs) & 255);
        float A = g_ab[c], Bv = g_ab[CC + c];
        float4 v = ((const float4*)g_y)[i];
        float4 o;
        o.x = fmaxf(fmaf(v.x, A, Bv), 0.0f);
        o.y = fmaxf(fmaf(v.y, A, Bv), 0.0f);
        o.z = fmaxf(fmaf(v.z, A, Bv), 0.0f);
        o.w = fmaxf(fmaf(v.w, A, Bv), 0.0f);
        ((float4*)out)[i] = o;
    }
}

// ---------------------------------------------------------------------------
// Launch (gemm is launch index 3 so the profiler lands on it)
// ---------------------------------------------------------------------------
extern "C" void kernel_launch(void* const* d_in, const int* in_sizes, int n_in,
                              void* d_out, int out_size) {
    (void)in_sizes; (void)n_in; (void)out_size;
    const float* x     = (const float*)d_in[0];
    const float* wt    = (const float*)d_in[1];
    const float* gamma = (const float*)d_in[2];
    const float* beta  = (const float*)d_in[3];
    float* out = (float*)d_out;

    static int smem_set = 0;
    if (!smem_set) {
        cudaFuncSetAttribute(gemm_kernel, cudaFuncAttributeMaxDynamicSharedMemorySize,
                             SMEM_DYN);
        smem_set = 1;
    }

    wprep_kernel<<<256, 256>>>(wt);
    border_kernel<<<dim3(228, 32), 256>>>();
    sign_transpose_kernel<<<dim3(56, 32), 256>>>(x);
    gemm_kernel<<<dim3(NTILES, 2), 256, SMEM_DYN>>>();
    coeff_kernel<<<1, 256>>>(gamma, beta);
    finalize_kernel<<<8192, 256>>>(out);
}

// round 4
// speedup vs baseline: 2.0774x; 2.0774x over previous
#include <cuda_runtime.h>
#include <cstdint>

// ---------------------------------------------------------------------------
// Problem constants
// ---------------------------------------------------------------------------
constexpr int BB = 32, CC = 256, HH = 56, WW = 56;
constexpr int HP = 58, WP = 58;                 // padded spatial
constexpr int HWs = HH * WW;                    // 3136
constexpr int CHW = CC * HWs;                   // 802816
constexpr int PIX = BB * HWs;                   // 100352
constexpr int KW  = 72;                         // K in 32-bit words (2304 bits)
constexpr int KBITS = 2304;
constexpr float BN_EPS = 1e-5f;

constexpr int TM = 64;                          // CTA pixel tile
constexpr int TN = 128;                         // CTA cout tile
constexpr int NT_M = PIX / TM;                  // 1568
// smem: W tile [72][128] words + X tile [72][64] words
constexpr int SW_WORDS = KW * TN;               // 9216
constexpr int SX_WORDS = KW * TM;               // 4608
constexpr int SMEM_DYN = (SW_WORDS + SX_WORDS) * 4;   // 55296 B

// ---------------------------------------------------------------------------
// Device scratch (allocation-free: __device__ globals)
// ---------------------------------------------------------------------------
__device__ uint32_t g_xp[(size_t)BB * HP * WP * 8];   // packed x, padded NHWC, 3.4MB
__device__ uint32_t g_wpT[KW * CC];                   // packed w, [k][cout]
__device__ int      g_corr[9 * CC];                   // border corrections
__device__ short    g_y16[(size_t)PIX * CC];          // conv result, NCHW int16, 51MB
__device__ float    g_scale[CC];
__device__ unsigned long long g_isum[CC];
__device__ unsigned long long g_isumsq[CC];
__device__ float    g_ab[2 * CC];

// ---------------------------------------------------------------------------
// Kernel: weight prep — scale, packed bits [k][o], border-correction table,
// and zero the integer BN accumulators.
// ---------------------------------------------------------------------------
__global__ void wprep_kernel(const float* __restrict__ w) {
    int o = blockIdx.x, tid = threadIdx.x;
    int lane = tid & 31, warp = tid >> 5;
    const float* wp = w + ((size_t)o * CC + tid) * 9;
    float v[9]; float s = 0.0f;
#pragma unroll
    for (int t = 0; t < 9; t++) { v[t] = wp[t]; s += fabsf(v[t]); }
#pragma unroll
    for (int off = 16; off; off >>= 1) s += __shfl_xor_sync(~0u, s, off);
    __shared__ float sh[8];
    __shared__ uint32_t words[9][8];
    __shared__ int S[9];
    if (lane == 0) sh[warp] = s;

    // pack: warp j supplies bits for channels j*32+lane, word index tap*8+j
#pragma unroll
    for (int t = 0; t < 9; t++) {
        uint32_t m = __ballot_sync(~0u, v[t] > 0.0f);
        if (lane == 0) words[t][warp] = m;
    }
    __syncthreads();
    if (tid == 0) {
        float tot = 0.0f;
        for (int i = 0; i < 8; i++) tot += sh[i];
        g_scale[o] = tot / (float)KBITS;
        g_isum[o] = 0ull; g_isumsq[o] = 0ull;
    }
    if (tid < 72) {
        int t = tid >> 3, j = tid & 7;
        g_wpT[(t * 8 + j) * CC + o] = words[t][j];
    }
    if (tid < 9) {
        int P = 0;
        for (int j = 0; j < 8; j++) P += __popc(words[tid][j]);
        S[tid] = 2 * P - 256;          // sum_ci sign(w[o][ci][tap])
    }
    __syncthreads();
    if (tid < 9) {                      // tid = border category ht*3+wt
        int ht = tid / 3, wt = tid % 3;
        int corr = 0;
        for (int kh = 0; kh < 3; kh++)
            for (int kw = 0; kw < 3; kw++) {
                bool miss = (ht == 0 && kh == 0) || (ht == 2 && kh == 2) ||
                            (wt == 0 && kw == 0) || (wt == 2 && kw == 2);
                if (miss) corr += S[kh * 3 + kw];
            }
        g_corr[tid * CC + o] = corr;
    }
}

// ---------------------------------------------------------------------------
// Kernel: zero packed-x buffer (pad ring stays 0 = "all -1", corrected later)
// ---------------------------------------------------------------------------
__global__ void zero_xp_kernel() {
    size_t i = (size_t)blockIdx.x * 256 + threadIdx.x;   // 215296 uint4
    ((uint4*)g_xp)[i] = make_uint4(0, 0, 0, 0);
}

// ---------------------------------------------------------------------------
// Kernel: pack sign bits of x: NCHW fp32 -> padded [b][h][w][8 words]
// warp j produces word j (channels j*32+lane), matching wprep's convention.
// ---------------------------------------------------------------------------
__global__ void xpack_kernel(const float* __restrict__ x) {
    int h = blockIdx.x, b = blockIdx.y;
    int lane = threadIdx.x & 31, warp = threadIdx.x >> 5;
    const float4* xrow =
        (const float4*)(x + (((size_t)(b * CC + warp * 32 + lane)) * HH + h) * WW);
    uint32_t* base = &g_xp[(((size_t)(b * HP + h + 1)) * WP + 1) * 8 + warp];
    for (int w0 = 0; w0 < WW; w0 += 4) {
        float4 v = xrow[w0 >> 2];
        uint32_t m0 = __ballot_sync(~0u, v.x > 0.0f);
        uint32_t m1 = __ballot_sync(~0u, v.y > 0.0f);
        uint32_t m2 = __ballot_sync(~0u, v.z > 0.0f);
        uint32_t m3 = __ballot_sync(~0u, v.w > 0.0f);
        if (lane == 0) {
            base[(w0 + 0) * 8] = m0; base[(w0 + 1) * 8] = m1;
            base[(w0 + 2) * 8] = m2; base[(w0 + 3) * 8] = m3;
        }
    }
}

// ---------------------------------------------------------------------------
// Kernel: XNOR-popcount implicit-GEMM conv + fused exact BN stats.
// CTA: 64 pixels x 128 couts. Thread: 4 pixels x 8 couts. K resident in smem.
// ---------------------------------------------------------------------------
__global__ __launch_bounds__(256, 3) void gemm_kernel() {
    extern __shared__ uint32_t smem[];
    uint32_t* sW = smem;                // [72][128]
    uint32_t* sX = smem + SW_WORDS;     // [72][64]

    const int tid = threadIdx.x;
    const int lane = tid & 31;
    const int p0 = blockIdx.x * TM;
    const int n0 = blockIdx.y * TN;

    // ---- load W tile (coalesced) ----
    {
        int col = tid & 127, khalf = tid >> 7;
        for (int k = khalf; k < KW; k += 2)
            sW[k * TN + col] = g_wpT[k * CC + n0 + col];
    }
    // ---- gather X tile: 64 pixels x 9 taps x 8 words ----
    for (int idx = tid; idx < 576; idx += 256) {
        int pix = idx & 63, tap = idx >> 6;
        int p = p0 + pix;
        int b = p / HWs, hw = p - b * HWs;
        int h = hw / WW, w = hw - h * WW;
        int kh = tap / 3, kw = tap - 3 * kh;
        const uint4* src =
            (const uint4*)&g_xp[(((size_t)(b * HP + h + kh)) * WP + (w + kw)) * 8];
        uint4 q0 = src[0], q1 = src[1];
        int kb = tap * 8;
        sX[(kb + 0) * TM + pix] = q0.x; sX[(kb + 1) * TM + pix] = q0.y;
        sX[(kb + 2) * TM + pix] = q0.z; sX[(kb + 3) * TM + pix] = q0.w;
        sX[(kb + 4) * TM + pix] = q1.x; sX[(kb + 5) * TM + pix] = q1.y;
        sX[(kb + 6) * TM + pix] = q1.z; sX[(kb + 7) * TM + pix] = q1.w;
    }
    __syncthreads();

    const int pg = tid & 15;    // pixel group: pixels pg*4..+3
    const int cg = tid >> 4;    // cout group:  couts cg*8..+7
    const uint4* sXv = (const uint4*)sX;   // row k: 16 uint4
    const uint4* sWv = (const uint4*)sW;   // row k: 32 uint4

    int acc[4][8];
#pragma unroll
    for (int i = 0; i < 4; i++)
#pragma unroll
        for (int j = 0; j < 8; j++) acc[i][j] = 0;

#pragma unroll 2
    for (int k = 0; k < KW; k += 2) {
        uint4 xq0 = sXv[k * 16 + pg];
        uint4 xq1 = sXv[(k + 1) * 16 + pg];
        uint4 wq00 = sWv[k * 32 + cg * 2];
        uint4 wq01 = sWv[k * 32 + cg * 2 + 1];
        uint4 wq10 = sWv[(k + 1) * 32 + cg * 2];
        uint4 wq11 = sWv[(k + 1) * 32 + cg * 2 + 1];
        uint32_t xs0[4] = {xq0.x, xq0.y, xq0.z, xq0.w};
        uint32_t xs1[4] = {xq1.x, xq1.y, xq1.z, xq1.w};
        uint32_t ws0[8] = {wq00.x, wq00.y, wq00.z, wq00.w,
                           wq01.x, wq01.y, wq01.z, wq01.w};
        uint32_t ws1[8] = {wq10.x, wq10.y, wq10.z, wq10.w,
                           wq11.x, wq11.y, wq11.z, wq11.w};
#pragma unroll
        for (int i = 0; i < 4; i++)
#pragma unroll
            for (int j = 0; j < 8; j++)
                acc[i][j] += __popc(xs0[i] ^ ws0[j]) + __popc(xs1[i] ^ ws1[j]);
    }

    // ---- epilogue: u = 2304 - 2*D + border correction ----
    int pcat[4];
#pragma unroll
    for (int i = 0; i < 4; i++) {
        int p = p0 + pg * 4 + i;
        int hw = p % HWs;
        int h = hw / WW, w = hw - h * WW;
        int ht = (h == 0) ? 0 : ((h == HH - 1) ? 2 : 1);
        int wt = (w == 0) ? 0 : ((w == WW - 1) ? 2 : 1);
        pcat[i] = ht * 3 + wt;
    }
    int u[4][8];
#pragma unroll
    for (int j = 0; j < 8; j++) {
        int c = n0 + cg * 8 + j;
#pragma unroll
        for (int i = 0; i < 4; i++) {
            int corr = (pcat[i] == 4) ? 0 : g_corr[pcat[i] * CC + c];
            u[i][j] = KBITS - 2 * acc[i][j] + corr;
        }
    }

    // ---- fused exact BN statistics (integer, order-independent) ----
#pragma unroll
    for (int j = 0; j < 8; j++) {
        int s = 0, s2 = 0;
#pragma unroll
        for (int i = 0; i < 4; i++) { s += u[i][j]; s2 += u[i][j] * u[i][j]; }
#pragma unroll
        for (int m = 1; m < 16; m <<= 1) {
            s  += __shfl_xor_sync(~0u, s, m);
            s2 += __shfl_xor_sync(~0u, s2, m);
        }
        if ((lane & 15) == 0) {
            int c = n0 + cg * 8 + j;
            atomicAdd(&g_isum[c],   (unsigned long long)(long long)s);
            atomicAdd(&g_isumsq[c], (unsigned long long)(long long)s2);
        }
    }

    // ---- store int16 conv result, NCHW ----
    {
        int p2 = p0 + pg * 4;
        int b2 = p2 / HWs, hw2 = p2 - b2 * HWs;
        short* yd = g_y16 + (size_t)b2 * CHW + hw2;
#pragma unroll
        for (int j = 0; j < 8; j++) {
            int c = n0 + cg * 8 + j;
            uint2 val;
            val.x = (uint32_t)(u[0][j] & 0xffff) | ((uint32_t)u[1][j] << 16);
            val.y = (uint32_t)(u[2][j] & 0xffff) | ((uint32_t)u[3][j] << 16);
            *(uint2*)&yd[(size_t)c * HWs] = val;
        }
    }
}

// ---------------------------------------------------------------------------
// Kernel: BN affine coefficients (exact integer stats, weight scale folded)
// ---------------------------------------------------------------------------
__global__ void coeff_kernel(const float* __restrict__ gamma, const float* __restrict__ beta) {
    int c = threadIdx.x;
    double n  = (double)PIX;
    double mu = (double)(long long)g_isum[c] / n;
    double vu = (double)(long long)g_isumsq[c] / n - mu * mu;
    double sc = (double)g_scale[c];
    double A  = (double)gamma[c] * sc / sqrt(sc * sc * vu + (double)BN_EPS);
    g_ab[c]      = (float)A;
    g_ab[CC + c] = (float)((double)beta[c] - A * mu);
}

// ---------------------------------------------------------------------------
// Kernel: out = relu(A*u + B), int16 -> fp32, NCHW
// ---------------------------------------------------------------------------
__global__ void finalize_kernel(float* __restrict__ out) {
    size_t idx = (size_t)blockIdx.x * 256 + threadIdx.x;   // one per 8 elems
    size_t j = idx * 8;
    int c = (int)((j / HWs) & 255);
    float A = g_ab[c], Bv = g_ab[CC + c];
    uint4 raw = ((const uint4*)g_y16)[idx];
    float4 o0, o1;
    o0.x = fmaxf(fmaf((float)(short)(raw.x & 0xffff), A, Bv), 0.0f);
    o0.y = fmaxf(fmaf((float)(short)(raw.x >> 16),    A, Bv), 0.0f);
    o0.z = fmaxf(fmaf((float)(short)(raw.y & 0xffff), A, Bv), 0.0f);
    o0.w = fmaxf(fmaf((float)(short)(raw.y >> 16),    A, Bv), 0.0f);
    o1.x = fmaxf(fmaf((float)(short)(raw.z & 0xffff), A, Bv), 0.0f);
    o1.y = fmaxf(fmaf((float)(short)(raw.z >> 16),    A, Bv), 0.0f);
    o1.z = fmaxf(fmaf((float)(short)(raw.w & 0xffff), A, Bv), 0.0f);
    o1.w = fmaxf(fmaf((float)(short)(raw.w >> 16),    A, Bv), 0.0f);
    ((float4*)out)[idx * 2]     = o0;
    ((float4*)out)[idx * 2 + 1] = o1;
}

// ---------------------------------------------------------------------------
// Launch (gemm is launch index 3 so the profiler lands on it)
// ---------------------------------------------------------------------------
extern "C" void kernel_launch(void* const* d_in, const int* in_sizes, int n_in,
                              void* d_out, int out_size) {
    (void)in_sizes; (void)n_in; (void)out_size;
    const float* x     = (const float*)d_in[0];
    const float* wt    = (const float*)d_in[1];
    const float* gamma = (const float*)d_in[2];
    const float* beta  = (const float*)d_in[3];
    float* out = (float*)d_out;

    static int smem_set = 0;
    if (!smem_set) {
        cudaFuncSetAttribute(gemm_kernel, cudaFuncAttributeMaxDynamicSharedMemorySize,
                             SMEM_DYN);
        smem_set = 1;
    }

    wprep_kernel<<<256, 256>>>(wt);
    zero_xp_kernel<<<(BB * HP * WP * 8 / 4) / 256, 256>>>();
    xpack_kernel<<<dim3(HH, BB), 256>>>(x);
    gemm_kernel<<<dim3(NT_M, 2), 256, SMEM_DYN>>>();
    coeff_kernel<<<1, 256>>>(gamma, beta);
    finalize_kernel<<<(int)((size_t)PIX * CC / 8 / 256), 256>>>(out);
}

// round 6
// speedup vs baseline: 2.0852x; 1.0038x over previous
#include <cuda_runtime.h>
#include <cstdint>

// ---------------------------------------------------------------------------
// Problem constants
// ---------------------------------------------------------------------------
constexpr int BB = 32, CC = 256, HH = 56, WW = 56;
constexpr int HP = 58, WP = 58;                 // padded spatial
constexpr int HWs = HH * WW;                    // 3136
constexpr int CHW = CC * HWs;                   // 802816
constexpr int PIX = BB * HWs;                   // 100352
constexpr int KW  = 72;                         // K in 32-bit words (2304 bits)
constexpr int KBITS = 2304;
constexpr float BN_EPS = 1e-5f;

constexpr int TM = 64;                          // CTA pixel tile
constexpr int TN = 128;                         // CTA cout tile
constexpr int NT_M = PIX / TM;                  // 1568
// smem: W tile [72][128] words + X tile [72][64] words
constexpr int SW_WORDS = KW * TN;               // 9216
constexpr int SX_WORDS = KW * TM;               // 4608
constexpr int SMEM_DYN = (SW_WORDS + SX_WORDS) * 4;   // 55296 B

// ---------------------------------------------------------------------------
// Device scratch (allocation-free: __device__ globals)
// ---------------------------------------------------------------------------
__device__ uint32_t g_xp[(size_t)BB * HP * WP * 8];   // packed x, padded NHWC, 3.4MB
__device__ uint32_t g_wpT[KW * CC];                   // packed w, [k][cout]
__device__ int      g_corr[9 * CC];                   // border corrections
__device__ short    g_y16[(size_t)PIX * CC];          // conv result, NCHW int16, 51MB
__device__ float    g_scale[CC];
__device__ unsigned long long g_isum[CC];
__device__ unsigned long long g_isumsq[CC];
__device__ float    g_ab[2 * CC];

// ---------------------------------------------------------------------------
// Kernel: weight prep — scale, packed bits [k][o], border-correction table,
// and zero the integer BN accumulators.
// ---------------------------------------------------------------------------
__global__ void wprep_kernel(const float* __restrict__ w) {
    int o = blockIdx.x, tid = threadIdx.x;
    int lane = tid & 31, warp = tid >> 5;
    const float* wp = w + ((size_t)o * CC + tid) * 9;
    float v[9]; float s = 0.0f;
#pragma unroll
    for (int t = 0; t < 9; t++) { v[t] = wp[t]; s += fabsf(v[t]); }
#pragma unroll
    for (int off = 16; off; off >>= 1) s += __shfl_xor_sync(~0u, s, off);
    __shared__ float sh[8];
    __shared__ uint32_t words[9][8];
    __shared__ int S[9];
    if (lane == 0) sh[warp] = s;

    // pack: warp j supplies bits for channels j*32+lane, word index tap*8+j
#pragma unroll
    for (int t = 0; t < 9; t++) {
        uint32_t m = __ballot_sync(~0u, v[t] > 0.0f);
        if (lane == 0) words[t][warp] = m;
    }
    __syncthreads();
    if (tid == 0) {
        float tot = 0.0f;
        for (int i = 0; i < 8; i++) tot += sh[i];
        g_scale[o] = tot / (float)KBITS;
        g_isum[o] = 0ull; g_isumsq[o] = 0ull;
    }
    if (tid < 72) {
        int t = tid >> 3, j = tid & 7;
        g_wpT[(t * 8 + j) * CC + o] = words[t][j];
    }
    if (tid < 9) {
        int P = 0;
        for (int j = 0; j < 8; j++) P += __popc(words[tid][j]);
        S[tid] = 2 * P - 256;          // sum_ci sign(w[o][ci][tap])
    }
    __syncthreads();
    if (tid < 9) {                      // tid = border category ht*3+wt
        int ht = tid / 3, wt = tid % 3;
        int corr = 0;
        for (int kh = 0; kh < 3; kh++)
            for (int kw = 0; kw < 3; kw++) {
                bool miss = (ht == 0 && kh == 0) || (ht == 2 && kh == 2) ||
                            (wt == 0 && kw == 0) || (wt == 2 && kw == 2);
                if (miss) corr += S[kh * 3 + kw];
            }
        g_corr[tid * CC + o] = corr;
    }
}

// ---------------------------------------------------------------------------
// Kernel: zero packed-x buffer (pad ring stays 0 = "all -1", corrected later)
// ---------------------------------------------------------------------------
__global__ void zero_xp_kernel() {
    size_t i = (size_t)blockIdx.x * 256 + threadIdx.x;   // 215296 uint4
    ((uint4*)g_xp)[i] = make_uint4(0, 0, 0, 0);
}

// ---------------------------------------------------------------------------
// Kernel: pack sign bits of x: NCHW fp32 -> padded [b][h][w][8 words]
// warp j produces word j (channels j*32+lane), matching wprep's convention.
// ---------------------------------------------------------------------------
__global__ void xpack_kernel(const float* __restrict__ x) {
    int h = blockIdx.x, b = blockIdx.y;
    int lane = threadIdx.x & 31, warp = threadIdx.x >> 5;
    const float4* xrow =
        (const float4*)(x + (((size_t)(b * CC + warp * 32 + lane)) * HH + h) * WW);
    uint32_t* base = &g_xp[(((size_t)(b * HP + h + 1)) * WP + 1) * 8 + warp];
    for (int w0 = 0; w0 < WW; w0 += 4) {
        float4 v = xrow[w0 >> 2];
        uint32_t m0 = __ballot_sync(~0u, v.x > 0.0f);
        uint32_t m1 = __ballot_sync(~0u, v.y > 0.0f);
        uint32_t m2 = __ballot_sync(~0u, v.z > 0.0f);
        uint32_t m3 = __ballot_sync(~0u, v.w > 0.0f);
        if (lane == 0) {
            base[(w0 + 0) * 8] = m0; base[(w0 + 1) * 8] = m1;
            base[(w0 + 2) * 8] = m2; base[(w0 + 3) * 8] = m3;
        }
    }
}

// ---------------------------------------------------------------------------
// Kernel: XNOR-popcount implicit-GEMM conv + fused exact BN stats.
// CTA: 64 pixels x 128 couts. Thread: 4 pixels x 8 couts. K resident in smem.
// 4 CTAs/SM (regs capped at 64): W staged 2 uint4 at a time.
// ---------------------------------------------------------------------------
__global__ __launch_bounds__(256, 4) void gemm_kernel() {
    extern __shared__ uint32_t smem[];
    uint32_t* sW = smem;                // [72][128]
    uint32_t* sX = smem + SW_WORDS;     // [72][64]

    const int tid = threadIdx.x;
    const int lane = tid & 31;
    const int p0 = blockIdx.x * TM;
    const int n0 = blockIdx.y * TN;

    // ---- load W tile (coalesced) ----
    {
        int col = tid & 127, khalf = tid >> 7;
        for (int k = khalf; k < KW; k += 2)
            sW[k * TN + col] = g_wpT[k * CC + n0 + col];
    }
    // ---- gather X tile: 64 pixels x 9 taps x 8 words ----
    for (int idx = tid; idx < 576; idx += 256) {
        int pix = idx & 63, tap = idx >> 6;
        int p = p0 + pix;
        int b = p / HWs, hw = p - b * HWs;
        int h = hw / WW, w = hw - h * WW;
        int kh = tap / 3, kw = tap - 3 * kh;
        const uint4* src =
            (const uint4*)&g_xp[(((size_t)(b * HP + h + kh)) * WP + (w + kw)) * 8];
        uint4 q0 = src[0], q1 = src[1];
        int kb = tap * 8;
        sX[(kb + 0) * TM + pix] = q0.x; sX[(kb + 1) * TM + pix] = q0.y;
        sX[(kb + 2) * TM + pix] = q0.z; sX[(kb + 3) * TM + pix] = q0.w;
        sX[(kb + 4) * TM + pix] = q1.x; sX[(kb + 5) * TM + pix] = q1.y;
        sX[(kb + 6) * TM + pix] = q1.z; sX[(kb + 7) * TM + pix] = q1.w;
    }
    __syncthreads();

    const int pg = tid & 15;    // pixel group: pixels pg*4..+3
    const int cg = tid >> 4;    // cout group:  couts cg*8..+7
    const uint4* sXv = (const uint4*)sX;   // row k: 16 uint4
    const uint4* sWv = (const uint4*)sW;   // row k: 32 uint4

    int acc[4][8];
#pragma unroll
    for (int i = 0; i < 4; i++)
#pragma unroll
        for (int j = 0; j < 8; j++) acc[i][j] = 0;

#pragma unroll 2
    for (int k = 0; k < KW; k += 2) {
        uint4 xq0 = sXv[k * 16 + pg];
        uint4 xq1 = sXv[(k + 1) * 16 + pg];
        uint32_t xs0[4] = {xq0.x, xq0.y, xq0.z, xq0.w};
        uint32_t xs1[4] = {xq1.x, xq1.y, xq1.z, xq1.w};
        // couts j = 0..3
        {
            uint4 w0 = sWv[k * 32 + cg * 2];
            uint4 w1 = sWv[(k + 1) * 32 + cg * 2];
            uint32_t ws0[4] = {w0.x, w0.y, w0.z, w0.w};
            uint32_t ws1[4] = {w1.x, w1.y, w1.z, w1.w};
#pragma unroll
            for (int i = 0; i < 4; i++)
#pragma unroll
                for (int j = 0; j < 4; j++)
                    acc[i][j] += __popc(xs0[i] ^ ws0[j]) + __popc(xs1[i] ^ ws1[j]);
        }
        // couts j = 4..7
        {
            uint4 w0 = sWv[k * 32 + cg * 2 + 1];
            uint4 w1 = sWv[(k + 1) * 32 + cg * 2 + 1];
            uint32_t ws0[4] = {w0.x, w0.y, w0.z, w0.w};
            uint32_t ws1[4] = {w1.x, w1.y, w1.z, w1.w};
#pragma unroll
            for (int i = 0; i < 4; i++)
#pragma unroll
                for (int j = 0; j < 4; j++)
                    acc[i][j + 4] += __popc(xs0[i] ^ ws0[j]) + __popc(xs1[i] ^ ws1[j]);
        }
    }

    // ---- epilogue: u = 2304 - 2*D + border correction ----
    int pcat[4];
#pragma unroll
    for (int i = 0; i < 4; i++) {
        int p = p0 + pg * 4 + i;
        int hw = p % HWs;
        int h = hw / WW, w = hw - h * WW;
        int ht = (h == 0) ? 0 : ((h == HH - 1) ? 2 : 1);
        int wt = (w == 0) ? 0 : ((w == WW - 1) ? 2 : 1);
        pcat[i] = ht * 3 + wt;
    }
    int u[4][8];
#pragma unroll
    for (int j = 0; j < 8; j++) {
        int c = n0 + cg * 8 + j;
#pragma unroll
        for (int i = 0; i < 4; i++) {
            int corr = (pcat[i] == 4) ? 0 : g_corr[pcat[i] * CC + c];
            u[i][j] = KBITS - 2 * acc[i][j] + corr;
        }
    }

    // ---- fused exact BN statistics (integer, order-independent) ----
#pragma unroll
    for (int j = 0; j < 8; j++) {
        int s = 0, s2 = 0;
#pragma unroll
        for (int i = 0; i < 4; i++) { s += u[i][j]; s2 += u[i][j] * u[i][j]; }
#pragma unroll
        for (int m = 1; m < 16; m <<= 1) {
            s  += __shfl_xor_sync(~0u, s, m);
            s2 += __shfl_xor_sync(~0u, s2, m);
        }
        if ((lane & 15) == 0) {
            int c = n0 + cg * 8 + j;
            atomicAdd(&g_isum[c],   (unsigned long long)(long long)s);
            atomicAdd(&g_isumsq[c], (unsigned long long)(long long)s2);
        }
    }

    // ---- store int16 conv result, NCHW ----
    {
        int p2 = p0 + pg * 4;
        int b2 = p2 / HWs, hw2 = p2 - b2 * HWs;
        short* yd = g_y16 + (size_t)b2 * CHW + hw2;
#pragma unroll
        for (int j = 0; j < 8; j++) {
            int c = n0 + cg * 8 + j;
            uint2 val;
            val.x = (uint32_t)(u[0][j] & 0xffff) | ((uint32_t)u[1][j] << 16);
            val.y = (uint32_t)(u[2][j] & 0xffff) | ((uint32_t)u[3][j] << 16);
            *(uint2*)&yd[(size_t)c * HWs] = val;
        }
    }
}

// ---------------------------------------------------------------------------
// Kernel: BN affine coefficients (exact integer stats, weight scale folded)
// ---------------------------------------------------------------------------
__global__ void coeff_kernel(const float* __restrict__ gamma, const float* __restrict__ beta) {
    int c = threadIdx.x;
    double n  = (double)PIX;
    double mu = (double)(long long)g_isum[c] / n;
    double vu = (double)(long long)g_isumsq[c] / n - mu * mu;
    double sc = (double)g_scale[c];
    double A  = (double)gamma[c] * sc / sqrt(sc * sc * vu + (double)BN_EPS);
    g_ab[c]      = (float)A;
    g_ab[CC + c] = (float)((double)beta[c] - A * mu);
}

// ---------------------------------------------------------------------------
// Kernel: out = relu(A*u + B), int16 -> fp32, NCHW
// ---------------------------------------------------------------------------
__global__ void finalize_kernel(float* __restrict__ out) {
    size_t idx = (size_t)blockIdx.x * 256 + threadIdx.x;   // one per 8 elems
    size_t j = idx * 8;
    int c = (int)((j / HWs) & 255);
    float A = g_ab[c], Bv = g_ab[CC + c];
    uint4 raw = ((const uint4*)g_y16)[idx];
    float4 o0, o1;
    o0.x = fmaxf(fmaf((float)(short)(raw.x & 0xffff), A, Bv), 0.0f);
    o0.y = fmaxf(fmaf((float)(short)(raw.x >> 16),    A, Bv), 0.0f);
    o0.z = fmaxf(fmaf((float)(short)(raw.y & 0xffff), A, Bv), 0.0f);
    o0.w = fmaxf(fmaf((float)(short)(raw.y >> 16),    A, Bv), 0.0f);
    o1.x = fmaxf(fmaf((float)(short)(raw.z & 0xffff), A, Bv), 0.0f);
    o1.y = fmaxf(fmaf((float)(short)(raw.z >> 16),    A, Bv), 0.0f);
    o1.z = fmaxf(fmaf((float)(short)(raw.w & 0xffff), A, Bv), 0.0f);
    o1.w = fmaxf(fmaf((float)(short)(raw.w >> 16),    A, Bv), 0.0f);
    ((float4*)out)[idx * 2]     = o0;
    ((float4*)out)[idx * 2 + 1] = o1;
}

// ---------------------------------------------------------------------------
// Launch (gemm is launch index 3 so the profiler lands on it)
// ---------------------------------------------------------------------------
extern "C" void kernel_launch(void* const* d_in, const int* in_sizes, int n_in,
                              void* d_out, int out_size) {
    (void)in_sizes; (void)n_in; (void)out_size;
    const float* x     = (const float*)d_in[0];
    const float* wt    = (const float*)d_in[1];
    const float* gamma = (const float*)d_in[2];
    const float* beta  = (const float*)d_in[3];
    float* out = (float*)d_out;

    static int smem_set = 0;
    if (!smem_set) {
        cudaFuncSetAttribute(gemm_kernel, cudaFuncAttributeMaxDynamicSharedMemorySize,
                             SMEM_DYN);
        smem_set = 1;
    }

    wprep_kernel<<<256, 256>>>(wt);
    zero_xp_kernel<<<(BB * HP * WP * 8 / 4) / 256, 256>>>();
    xpack_kernel<<<dim3(HH, BB), 256>>>(x);
    gemm_kernel<<<dim3(NT_M, 2), 256, SMEM_DYN>>>();
    coeff_kernel<<<1, 256>>>(gamma, beta);
    finalize_kernel<<<(int)((size_t)PIX * CC / 8 / 256), 256>>>(out);
}